// round 1
// baseline (speedup 1.0000x reference)
#include <cuda_runtime.h>
#include <math.h>

#define NN 50000
#define NE 800000
#define DF 64
#define MM 11
#define NDEPTH 3

// ---------------- scratch (device globals — no allocation allowed) ----------
__device__ int   g_cnt[NN];
__device__ int   g_cur[NN];
__device__ int   g_rowptr[NN + 1];
__device__ float g_dinv[NN];
__device__ int2  g_edge[NE];          // (col, val-bits) packed per CSR slot
__device__ float g_y1[NN * DF];
__device__ float g_y2[NN * DF];
__device__ float g_y3[NN * DF];
__device__ float g_C[4][4];           // combined coefficients: out[L] = sum_k C[L][k] * S^k x

// ---------------- setup kernels ---------------------------------------------
__global__ void zero_kernel() {
    int i = blockIdx.x * blockDim.x + threadIdx.x;
    if (i < NN) { g_cnt[i] = 0; g_cur[i] = 0; }
}

__global__ void hist_kernel(const int* __restrict__ row) {
    int e = blockIdx.x * blockDim.x + threadIdx.x;
    if (e < NE) atomicAdd(&g_cnt[row[e]], 1);
}

__global__ void dinv_kernel() {
    int n = blockIdx.x * blockDim.x + threadIdx.x;
    if (n < NN) {
        float d = (float)g_cnt[n];
        if (d < 0.5f) d += 1.0f;
        g_dinv[n] = 1.0f / sqrtf(d);
    }
}

// single-block exclusive scan of g_cnt -> g_rowptr
__global__ void scan_kernel() {
    const int T = 1024;
    __shared__ int ssum[T];
    int t = threadIdx.x;
    const int per = (NN + T - 1) / T;   // 49
    int beg = t * per;
    int end = beg + per; if (end > NN) end = NN;
    int s = 0;
    for (int i = beg; i < end; i++) s += g_cnt[i];
    ssum[t] = s;
    __syncthreads();
    // Hillis-Steele inclusive scan
    for (int off = 1; off < T; off <<= 1) {
        int v = 0;
        if (t >= off) v = ssum[t - off];
        __syncthreads();
        ssum[t] += v;
        __syncthreads();
    }
    int run = (t == 0) ? 0 : ssum[t - 1];
    for (int i = beg; i < end; i++) {
        int c = g_cnt[i];
        g_rowptr[i] = run;
        run += c;
    }
    if (t == T - 1) g_rowptr[NN] = ssum[T - 1];
}

__global__ void scatter_kernel(const int* __restrict__ row,
                               const int* __restrict__ col,
                               const float* __restrict__ attr) {
    int e = blockIdx.x * blockDim.x + threadIdx.x;
    if (e >= NE) return;
    int r = row[e], c = col[e];
    float v = g_dinv[r] * attr[e] * g_dinv[c];
    int pos = g_rowptr[r] + atomicAdd(&g_cur[r], 1);
    g_edge[pos] = make_int2(c, __float_as_int(v));
}

// ---------------- coefficient kernel ----------------------------------------
// Jacobi recursion with l=-1, r=1: (l+r)/(r-l)=0, 2/(r-l)=1.
// P0 = 1
// P1 = al0*(coef1 + coef2*t),  coef1=(a-b)/2, coef2=(a+b+2)/2
// PL = tmp1 * t*P_{L-1} - tmp2 * P_{L-1} - tmp3 * P_{L-2}
__global__ void coeff_kernel(const float* __restrict__ alphas,
                             const float* __restrict__ w,
                             const float* __restrict__ a_arr,
                             const float* __restrict__ b_arr) {
    if (threadIdx.x != 0 || blockIdx.x != 0) return;
    double C[4][4];
    for (int i = 0; i < 4; i++)
        for (int k = 0; k < 4; k++) C[i][k] = 0.0;

    for (int m = 0; m < MM; m++) {
        double a = (double)a_arr[m];
        double b = (double)b_arr[m];
        double wm = (double)w[m];
        double al[NDEPTH];
        for (int d = 0; d < NDEPTH; d++) al[d] = (double)alphas[d * MM + m];

        double Pm2[4] = {1.0, 0.0, 0.0, 0.0};       // P0
        double coef1 = (a - b) * 0.5;
        double coef2 = (a + b + 2.0) * 0.5;
        double Pm1[4] = {al[0] * coef1, al[0] * coef2, 0.0, 0.0};  // P1

        for (int k = 0; k < 4; k++) C[0][k] += wm * Pm2[k];
        for (int k = 0; k < 4; k++) C[1][k] += wm * Pm1[k];

        for (int Lk = 2; Lk <= NDEPTH; Lk++) {
            double Lf = (double)Lk;
            double coef_l     = 2.0 * Lf * (Lf + a + b) * (2.0 * Lf - 2.0 + a + b);
            double coef_lm1_1 = (2.0 * Lf + a + b - 1.0) * (2.0 * Lf + a + b) * (2.0 * Lf + a + b - 2.0);
            double coef_lm1_2 = (2.0 * Lf + a + b - 1.0) * (a * a - b * b);
            double coef_lm2   = 2.0 * (Lf - 1.0 + a) * (Lf - 1.0 + b) * (2.0 * Lf + a + b);
            double alL   = al[Lk - 1];
            double alLm1 = al[Lk - 2];
            double tmp1 = alL * (coef_lm1_1 / coef_l);
            double tmp2 = alL * (coef_lm1_2 / coef_l);
            double tmp3 = alL * alLm1 * (coef_lm2 / coef_l);
            double PL[4];
            PL[0] = -tmp2 * Pm1[0] - tmp3 * Pm2[0];
            for (int k = 1; k < 4; k++)
                PL[k] = tmp1 * Pm1[k - 1] - tmp2 * Pm1[k] - tmp3 * Pm2[k];
            for (int k = 0; k < 4; k++) C[Lk][k] += wm * PL[k];
            for (int k = 0; k < 4; k++) { Pm2[k] = Pm1[k]; Pm1[k] = PL[k]; }
        }
    }
    for (int i = 0; i < 4; i++)
        for (int k = 0; k < 4; k++)
            g_C[i][k] = (float)C[i][k];
}

// ---------------- SpMM: y = S x (CSR), 16 threads/node, float4 lanes --------
// src: 0 = external x, 1 = g_y1, 2 = g_y2 ; dst: 1..3 -> g_y1..g_y3
__global__ void spmm_kernel(const float* __restrict__ xext, int src, int dst) {
    int gt = blockIdx.x * blockDim.x + threadIdx.x;
    int node = gt >> 4;
    if (node >= NN) return;
    int lane = gt & 15;

    const float* x = (src == 0) ? xext : (src == 1) ? g_y1 : g_y2;
    float* y = (dst == 1) ? g_y1 : (dst == 2) ? g_y2 : g_y3;

    int j   = g_rowptr[node];
    int end = g_rowptr[node + 1];

    const float4* x4 = (const float4*)x;
    float4 acc = make_float4(0.f, 0.f, 0.f, 0.f);

    for (; j + 2 <= end; j += 2) {
        int2 e0 = g_edge[j];
        int2 e1 = g_edge[j + 1];
        float v0 = __int_as_float(e0.y);
        float v1 = __int_as_float(e1.y);
        float4 a0 = __ldg(x4 + e0.x * 16 + lane);
        float4 a1 = __ldg(x4 + e1.x * 16 + lane);
        acc.x = fmaf(v0, a0.x, acc.x);
        acc.y = fmaf(v0, a0.y, acc.y);
        acc.z = fmaf(v0, a0.z, acc.z);
        acc.w = fmaf(v0, a0.w, acc.w);
        acc.x = fmaf(v1, a1.x, acc.x);
        acc.y = fmaf(v1, a1.y, acc.y);
        acc.z = fmaf(v1, a1.z, acc.z);
        acc.w = fmaf(v1, a1.w, acc.w);
    }
    if (j < end) {
        int2 e0 = g_edge[j];
        float v0 = __int_as_float(e0.y);
        float4 a0 = __ldg(x4 + e0.x * 16 + lane);
        acc.x = fmaf(v0, a0.x, acc.x);
        acc.y = fmaf(v0, a0.y, acc.y);
        acc.z = fmaf(v0, a0.z, acc.z);
        acc.w = fmaf(v0, a0.w, acc.w);
    }
    ((float4*)y)[node * 16 + lane] = acc;
}

// ---------------- output: out[n][L][d] = sum_k C[L][k] * (S^k x)[n][d] ------
__global__ void out_kernel(const float* __restrict__ x, float* __restrict__ out) {
    int gt = blockIdx.x * blockDim.x + threadIdx.x;
    if (gt >= NN * 16) return;
    int node = gt >> 4;
    int lane = gt & 15;
    int idx = node * 16 + lane;

    float4 v0 = ((const float4*)x)[idx];
    float4 v1 = ((const float4*)g_y1)[idx];
    float4 v2 = ((const float4*)g_y2)[idx];
    float4 v3 = ((const float4*)g_y3)[idx];

    float4* op = (float4*)out + node * 64 + lane;  // 256 floats/node = 64 float4
#pragma unroll
    for (int L = 0; L < 4; L++) {
        float c0 = g_C[L][0], c1 = g_C[L][1], c2 = g_C[L][2], c3 = g_C[L][3];
        float4 r;
        r.x = c0 * v0.x + c1 * v1.x + c2 * v2.x + c3 * v3.x;
        r.y = c0 * v0.y + c1 * v1.y + c2 * v2.y + c3 * v3.y;
        r.z = c0 * v0.z + c1 * v1.z + c2 * v2.z + c3 * v3.z;
        r.w = c0 * v0.w + c1 * v1.w + c2 * v2.w + c3 * v3.w;
        op[L * 16] = r;
    }
}

// ---------------- launcher ---------------------------------------------------
extern "C" void kernel_launch(void* const* d_in, const int* in_sizes, int n_in,
                              void* d_out, int out_size) {
    const float* x      = (const float*)d_in[0];
    const int*   ei     = (const int*)d_in[1];
    const int*   row    = ei;
    const int*   col    = ei + NE;
    const float* attr   = (const float*)d_in[2];
    const float* alphas = (const float*)d_in[3];
    const float* w      = (const float*)d_in[4];
    const float* a_arr  = (const float*)d_in[5];
    const float* b_arr  = (const float*)d_in[6];
    float*       out    = (float*)d_out;

    zero_kernel<<<(NN + 255) / 256, 256>>>();
    hist_kernel<<<(NE + 255) / 256, 256>>>(row);
    scan_kernel<<<1, 1024>>>();
    dinv_kernel<<<(NN + 255) / 256, 256>>>();
    scatter_kernel<<<(NE + 255) / 256, 256>>>(row, col, attr);
    coeff_kernel<<<1, 32>>>(alphas, w, a_arr, b_arr);

    const int spmm_threads = NN * 16;
    spmm_kernel<<<(spmm_threads + 255) / 256, 256>>>(x, 0, 1);  // y1 = S x
    spmm_kernel<<<(spmm_threads + 255) / 256, 256>>>(x, 1, 2);  // y2 = S y1
    spmm_kernel<<<(spmm_threads + 255) / 256, 256>>>(x, 2, 3);  // y3 = S y2

    out_kernel<<<(NN * 16 + 255) / 256, 256>>>(x, out);
}